// round 2
// baseline (speedup 1.0000x reference)
#include <cuda_runtime.h>
#include <cuda_bf16.h>

#define NN 100000
#define NE 3200000
#define DF 512
#define HID 16
#define NC 7

// ---------------- scratch (no allocations allowed) ----------------
__device__ float g_deg[NN];
__device__ float g_dinv[NN];
__device__ __align__(16) float g_h1[NN * HID];   // x @ W1
__device__ __align__(16) float g_m1[NN * HID];   // aggregated layer1
__device__ __align__(16) float g_t2[NN * 8];     // relu(m1+b1) @ W2, padded to 8
__device__ __align__(16) float g_m2[NN * 8];     // aggregated layer2, padded

// 128-bit global float reduction (sm_90+)
__device__ __forceinline__ void red_add_v4(float* p, float4 v) {
    asm volatile(
        "{\n\t"
        ".reg .u64 pg;\n\t"
        "cvta.to.global.u64 pg, %0;\n\t"
        "red.global.add.v4.f32 [pg], {%1,%2,%3,%4};\n\t"
        "}"
        :: "l"(p), "f"(v.x), "f"(v.y), "f"(v.z), "f"(v.w)
        : "memory");
}

// ---------------- K0: init accumulators ----------------
__global__ void k_init() {
    int i = blockIdx.x * blockDim.x + threadIdx.x;
    if (i < NN) g_deg[i] = 1.0f;          // self-loop contributes 1 to degree
    if (i < NN * HID) g_m1[i] = 0.0f;
    if (i < NN * 8) g_m2[i] = 0.0f;
}

// ---------------- K1: in-degree ----------------
__global__ void k_deg(const int* __restrict__ ei) {
    int e = blockIdx.x * blockDim.x + threadIdx.x;
    if (e < NE) {
        int dst = ei[NE + e];
        atomicAdd(&g_deg[dst], 1.0f);
    }
}

// ---------------- K2: dinv ----------------
__global__ void k_dinv() {
    int i = blockIdx.x * blockDim.x + threadIdx.x;
    if (i < NN) g_dinv[i] = rsqrtf(g_deg[i]);   // deg >= 1 always
}

// ---------------- K3: h1 = x @ W1  (100000x512 @ 512x16) ----------------
// Block: 256 threads, 64 rows x 16 cols per block. Thread t: row = t>>2, colgroup = t&3.
__global__ void k_gemm1(const float* __restrict__ x, const float* __restrict__ W1) {
    __shared__ float4 Ws[DF][4];      // full W1, 32 KB
    __shared__ float xs[64][36];      // 64-row x 32-col tile, padded (+4) vs bank conflicts

    int t = threadIdx.x;
    const float4* W4 = (const float4*)W1;
    #pragma unroll
    for (int i = t; i < DF * 4; i += 256)
        Ws[i >> 2][i & 3] = W4[i];

    int row0 = blockIdx.x * 64;
    int r  = t >> 2;
    int cg = t & 3;
    float4 acc = make_float4(0.f, 0.f, 0.f, 0.f);

    for (int kc = 0; kc < DF; kc += 32) {
        __syncthreads();
        #pragma unroll
        for (int it = 0; it < 2; it++) {
            int i  = t + it * 256;
            int rr = i >> 3, cc = i & 7;
            int grow = row0 + rr;
            float4 v = make_float4(0.f, 0.f, 0.f, 0.f);
            if (grow < NN) v = *(const float4*)&x[grow * DF + kc + cc * 4];
            *(float4*)&xs[rr][cc * 4] = v;
        }
        __syncthreads();
        #pragma unroll
        for (int k = 0; k < 32; k++) {
            float xv = xs[r][k];
            float4 w = Ws[kc + k][cg];
            acc.x += xv * w.x;
            acc.y += xv * w.y;
            acc.z += xv * w.z;
            acc.w += xv * w.w;
        }
    }
    int grow = row0 + r;
    if (grow < NN)
        *(float4*)&g_h1[grow * HID + cg * 4] = acc;
}

// ---------------- K4: layer-1 scatter: m1[dst] += h1[src] * w ----------------
// 4 threads per edge, one v4 reduction each.
__global__ void k_scat1(const int* __restrict__ ei) {
    int t = blockIdx.x * blockDim.x + threadIdx.x;
    int e = t >> 2, sub = t & 3;
    if (e >= NE) return;
    int src = ei[e];
    int dst = ei[NE + e];
    float w = g_dinv[src] * g_dinv[dst];
    float4 h = ((const float4*)g_h1)[src * 4 + sub];
    h.x *= w; h.y *= w; h.z *= w; h.w *= w;
    red_add_v4(&g_m1[dst * HID + sub * 4], h);
}

// ---------------- K5: h2 = relu(m1 + selfloop + b1); t2 = h2 @ W2 ----------------
__global__ void k_layer2(const float* __restrict__ b1, const float* __restrict__ W2) {
    __shared__ float W2s[HID][8];
    __shared__ float b1s[HID];
    int t = threadIdx.x;
    if (t < HID * NC) W2s[t / NC][t % NC] = W2[t];
    if (t < HID) { W2s[t][7] = 0.0f; b1s[t] = b1[t]; }
    __syncthreads();

    int n = blockIdx.x * blockDim.x + t;
    if (n >= NN) return;
    float dv = g_dinv[n];
    float d2 = dv * dv;

    float h[HID];
    #pragma unroll
    for (int j = 0; j < 4; j++) {
        float4 mv = ((const float4*)g_m1)[n * 4 + j];
        float4 hv = ((const float4*)g_h1)[n * 4 + j];
        float v0 = mv.x + hv.x * d2 + b1s[4 * j + 0];
        float v1 = mv.y + hv.y * d2 + b1s[4 * j + 1];
        float v2 = mv.z + hv.z * d2 + b1s[4 * j + 2];
        float v3 = mv.w + hv.w * d2 + b1s[4 * j + 3];
        h[4 * j + 0] = fmaxf(v0, 0.f);
        h[4 * j + 1] = fmaxf(v1, 0.f);
        h[4 * j + 2] = fmaxf(v2, 0.f);
        h[4 * j + 3] = fmaxf(v3, 0.f);
    }

    float o[8];
    #pragma unroll
    for (int c = 0; c < 8; c++) o[c] = 0.f;
    #pragma unroll
    for (int k = 0; k < HID; k++) {
        #pragma unroll
        for (int c = 0; c < 8; c++)
            o[c] += h[k] * W2s[k][c];    // col 7 stays 0 (W2s[k][7]==0)
    }
    ((float4*)g_t2)[n * 2 + 0] = make_float4(o[0], o[1], o[2], o[3]);
    ((float4*)g_t2)[n * 2 + 1] = make_float4(o[4], o[5], o[6], o[7]);
}

// ---------------- K6: layer-2 scatter: m2[dst] += t2[src] * w ----------------
// 2 threads per edge, one v4 reduction each.
__global__ void k_scat2(const int* __restrict__ ei) {
    int t = blockIdx.x * blockDim.x + threadIdx.x;
    int e = t >> 1, sub = t & 1;
    if (e >= NE) return;
    int src = ei[e];
    int dst = ei[NE + e];
    float w = g_dinv[src] * g_dinv[dst];
    float4 v = ((const float4*)g_t2)[src * 2 + sub];
    v.x *= w; v.y *= w; v.z *= w; v.w *= w;
    red_add_v4(&g_m2[dst * 8 + sub * 4], v);
}

// ---------------- K7: finalize: + selfloop + b2, log_softmax ----------------
__global__ void k_final(const float* __restrict__ b2, float* __restrict__ out) {
    int n = blockIdx.x * blockDim.x + threadIdx.x;
    if (n >= NN) return;
    float dv = g_dinv[n];
    float d2 = dv * dv;

    float4 m0 = ((const float4*)g_m2)[n * 2 + 0];
    float4 m1v = ((const float4*)g_m2)[n * 2 + 1];
    float4 t0 = ((const float4*)g_t2)[n * 2 + 0];
    float4 t1 = ((const float4*)g_t2)[n * 2 + 1];

    float l[NC];
    l[0] = m0.x + t0.x * d2 + b2[0];
    l[1] = m0.y + t0.y * d2 + b2[1];
    l[2] = m0.z + t0.z * d2 + b2[2];
    l[3] = m0.w + t0.w * d2 + b2[3];
    l[4] = m1v.x + t1.x * d2 + b2[4];
    l[5] = m1v.y + t1.y * d2 + b2[5];
    l[6] = m1v.z + t1.z * d2 + b2[6];

    float mx = l[0];
    #pragma unroll
    for (int c = 1; c < NC; c++) mx = fmaxf(mx, l[c]);
    float s = 0.f;
    #pragma unroll
    for (int c = 0; c < NC; c++) s += expf(l[c] - mx);
    float lse = mx + logf(s);
    #pragma unroll
    for (int c = 0; c < NC; c++) out[n * NC + c] = l[c] - lse;
}

// ---------------- launch ----------------
extern "C" void kernel_launch(void* const* d_in, const int* in_sizes, int n_in,
                              void* d_out, int out_size) {
    const float* x   = (const float*)d_in[0];
    const int*   ei  = (const int*)d_in[1];
    const float* W1  = (const float*)d_in[2];
    const float* b1  = (const float*)d_in[3];
    const float* W2  = (const float*)d_in[4];
    const float* b2  = (const float*)d_in[5];
    float*       out = (float*)d_out;

    k_init<<<(NN * HID + 255) / 256, 256>>>();
    k_deg<<<(NE + 255) / 256, 256>>>(ei);
    k_dinv<<<(NN + 255) / 256, 256>>>();
    k_gemm1<<<(NN + 63) / 64, 256>>>(x, W1);
    k_scat1<<<(NE * 4 + 255) / 256, 256>>>(ei);
    k_layer2<<<(NN + 255) / 256, 256>>>(b1, W2);
    k_scat2<<<(NE * 2 + 255) / 256, 256>>>(ei);
    k_final<<<(NN + 255) / 256, 256>>>(b2, out);
}